// round 14
// baseline (speedup 1.0000x reference)
#include <cuda_runtime.h>

// filtfilt (5-tap butter-style IIR, odd ext padlen=15) over 512 rows, T=32768.
//
// R14: block-segment FUSED kernel. A block owns 128 chunks (8192 samples) of
// one row: forward pass writes its results into a skew-indexed smem segment
// (u -> u + u/64: lane stride 64 becomes 65 -> conflict-free scalar LDS/STS);
// warp 3 computes a 32-sample extension past the segment end (state already
// converged). After one __syncthreads the SAME block runs the backward pass
// reading seg directly in compute order — no global scratch at all.
// Eliminates ~174MB of DRAM/L2 round-trip and bwd's entire load phase.
// Row top is exact: bwd truly starts at t=TEXT-1 with zero state.
// WARM=32, CH=64 (3 tiles/pass); measured rel_err ~1.65e-4 (gate 1e-3).
// Reference's per-row scale/descale is a linear no-op, skipped.

#define T_LEN   32768
#define PAD     15
#define TEXT    (T_LEN + 2 * PAD)    // 32798
#define CH      64
#define WARM    32
#define TILES   3                    // WARM+CH = 96 = 3*32
#define WPB     4
#define BLOCK   (WPB * 32)           // 128
#define CPB     (WPB * 32)           // chunks per block = 128
#define BPR     5                    // 4 full blocks + 1 stub per row
#define SEG_SAMP (CPB * CH + WARM)   // 8224 (incl. 32-sample extension)
#define SEG_IDX(u) ((u) + ((u) >> 6))
#define SEG_F   (SEG_SAMP + (SEG_SAMP >> 6) + 4)   // 8356
#define TW      36
#define SMEM_BYTES ((SEG_F + WPB * 32 * TW) * 4)   // 51856

#define LD128(p)    (*reinterpret_cast<const float4*>(p))
#define ST128(p, v) (*reinterpret_cast<float4*>(p) = (v))

struct Coef {
    float b0, b1, b2, b3, b4;
    float na1, na2, na3, na4;
};

__device__ __forceinline__ Coef load_coef(const float* __restrict__ bc,
                                          const float* __restrict__ ac) {
    Coef c;
    float inva0 = 1.0f / ac[0];
    c.b0 = bc[0] * inva0; c.b1 = bc[1] * inva0; c.b2 = bc[2] * inva0;
    c.b3 = bc[3] * inva0; c.b4 = bc[4] * inva0;
    c.na1 = -ac[1] * inva0; c.na2 = -ac[2] * inva0;
    c.na3 = -ac[3] * inva0; c.na4 = -ac[4] * inva0;
    return c;
}

// Direct-Form-I step; critical chain is the final fma through y1 (4 cyc).
#define IIR_STEP(xt)                                                   \
    do {                                                               \
        float f = fmaf(c.b0, (xt), fmaf(c.b1, x1,                      \
                  fmaf(c.b2, x2, fmaf(c.b3, x3, c.b4 * x4))));         \
        float s_ = fmaf(c.na2, y2, fmaf(c.na3, y3,                     \
                   fmaf(c.na4, y4, f)));                               \
        float y = fmaf(c.na1, y1, s_);                                 \
        x4 = x3; x3 = x2; x2 = x1; x1 = (xt);                          \
        y4 = y3; y3 = y2; y2 = y1; y1 = y;                             \
    } while (0)

// fwd: 8 steps reading tile octet, storing to seg (scalar, conflict-free).
#define FWD_OCTET(jb, do_store, sb)                                    \
    do {                                                               \
        float4 va = LD128(&sm[lane][jb]);                              \
        float4 vb = LD128(&sm[lane][(jb) + 4]);                        \
        IIR_STEP(va.x); if (do_store) seg[(sb) + (jb) + 0] = y1;       \
        IIR_STEP(va.y); if (do_store) seg[(sb) + (jb) + 1] = y1;       \
        IIR_STEP(va.z); if (do_store) seg[(sb) + (jb) + 2] = y1;       \
        IIR_STEP(va.w); if (do_store) seg[(sb) + (jb) + 3] = y1;       \
        IIR_STEP(vb.x); if (do_store) seg[(sb) + (jb) + 4] = y1;       \
        IIR_STEP(vb.y); if (do_store) seg[(sb) + (jb) + 5] = y1;       \
        IIR_STEP(vb.z); if (do_store) seg[(sb) + (jb) + 6] = y1;       \
        IIR_STEP(vb.w); if (do_store) seg[(sb) + (jb) + 7] = y1;       \
    } while (0)

// ext: 8 steps reading tile octet; only lane 31's results land in seg.
#define EXT_OCTET(jb, sbx)                                             \
    do {                                                               \
        float4 va = LD128(&sm[lane][jb]);                              \
        float4 vb = LD128(&sm[lane][(jb) + 4]);                        \
        IIR_STEP(va.x); if (lane == 31) seg[(sbx) + (jb) + 0] = y1;    \
        IIR_STEP(va.y); if (lane == 31) seg[(sbx) + (jb) + 1] = y1;    \
        IIR_STEP(va.z); if (lane == 31) seg[(sbx) + (jb) + 2] = y1;    \
        IIR_STEP(va.w); if (lane == 31) seg[(sbx) + (jb) + 3] = y1;    \
        IIR_STEP(vb.x); if (lane == 31) seg[(sbx) + (jb) + 4] = y1;    \
        IIR_STEP(vb.y); if (lane == 31) seg[(sbx) + (jb) + 5] = y1;    \
        IIR_STEP(vb.z); if (lane == 31) seg[(sbx) + (jb) + 6] = y1;    \
        IIR_STEP(vb.w); if (lane == 31) seg[(sbx) + (jb) + 7] = y1;    \
    } while (0)

// bwd: 8 steps reading seg (scalar desc, conflict-free), results to tile.
#define BWD_OCTET(jb, do_store, sb)                                    \
    do {                                                               \
        float v0 = seg[(sb) - ((jb) + 0)];                             \
        float v1 = seg[(sb) - ((jb) + 1)];                             \
        float v2 = seg[(sb) - ((jb) + 2)];                             \
        float v3 = seg[(sb) - ((jb) + 3)];                             \
        float v4 = seg[(sb) - ((jb) + 4)];                             \
        float v5 = seg[(sb) - ((jb) + 5)];                             \
        float v6 = seg[(sb) - ((jb) + 6)];                             \
        float v7 = seg[(sb) - ((jb) + 7)];                             \
        float4 wa, wb;                                                 \
        IIR_STEP(v0); wa.x = y1; IIR_STEP(v1); wa.y = y1;              \
        IIR_STEP(v2); wa.z = y1; IIR_STEP(v3); wa.w = y1;              \
        IIR_STEP(v4); wb.x = y1; IIR_STEP(v5); wb.y = y1;              \
        IIR_STEP(v6); wb.z = y1; IIR_STEP(v7); wb.w = y1;              \
        if (do_store) {                                                \
            ST128(&sm[lane][jb], wa);                                  \
            ST128(&sm[lane][(jb) + 4], wb);                            \
        }                                                              \
    } while (0)

// Odd-extended input at extended index t; 0 outside [0, TEXT).
__device__ __forceinline__ float load_xe_safe(const float* __restrict__ xr, int t) {
    if (t < 0)            return 0.0f;
    if (t < PAD)          return 2.0f * xr[0]         - xr[PAD - t];
    if (t < T_LEN + PAD)  return xr[t - PAD];
    if (t < TEXT)         return 2.0f * xr[T_LEN - 1] - xr[2 * T_LEN + PAD - 2 - t];
    return 0.0f;
}

__global__ void __launch_bounds__(BLOCK)
filt_kernel(const float* __restrict__ x,
            const float* __restrict__ bc,
            const float* __restrict__ ac,
            float* __restrict__ out) {
    extern __shared__ float smem_dyn[];
    float* seg = smem_dyn;
    int wib  = threadIdx.x >> 5;
    int lane = threadIdx.x & 31;
    float (*sm)[TW] = (float (*)[TW])(smem_dyn + SEG_F + wib * (32 * TW));

    int row = blockIdx.x / BPR;
    int b   = blockIdx.x - row * BPR;
    int A   = b * (CPB * CH);              // block segment base (ext index)
    const float* xr   = x   + (size_t)row * T_LEN;
    float*       orow = out + (size_t)row * T_LEN;
    Coef c = load_coef(bc, ac);

    int c0   = wib * 32;                   // warp's first (block-local) chunk
    int q    = c0 + lane;                  // this lane's chunk
    int base = A + c0 * CH - WARM;         // lane-0 window start

    // ================= forward pass =================
    if (base < TEXT) {                     // stub-block warps 1..3 skip
        bool fast = (b < BPR - 1) && !(b == 0 && wib == 0);
        float x1 = 0.f, x2 = 0.f, x3 = 0.f, x4 = 0.f;
        float y1 = 0.f, y2 = 0.f, y3 = 0.f, y4 = 0.f;
        int fb0 = SEG_IDX(q * CH);         // seg addr of lane's first emit

        #pragma unroll
        for (int tl = 0; tl < TILES; ++tl) {
            int off = tl * 32;
            if (fast) {
                const float* p = xr + (base - PAD) + off + lane;
                #pragma unroll 8
                for (int i = 0; i < 32; ++i) sm[i][lane] = p[i * CH];
            } else {
                #pragma unroll 4
                for (int i = 0; i < 32; ++i)
                    sm[i][lane] = load_xe_safe(xr, base + i * CH + off + lane);
            }
            __syncwarp();
            if (tl == 0) {
                FWD_OCTET(0,  false, 0); FWD_OCTET(8,  false, 0);
                FWD_OCTET(16, false, 0); FWD_OCTET(24, false, 0);
            } else {
                int sb = fb0 + (tl - 1) * 32;   // no 64-crossing inside a tile
                FWD_OCTET(0,  true, sb); FWD_OCTET(8,  true, sb);
                FWD_OCTET(16, true, sb); FWD_OCTET(24, true, sb);
            }
            __syncwarp();
        }
        // extension: warp WPB-1 continues 32 samples past segment end
        // (lane 31's state is converged; its outputs fill seg[u>=CPB*CH]).
        if (wib == WPB - 1 && A + CPB * CH < TEXT) {
            #pragma unroll 4
            for (int i = 0; i < 32; ++i)
                sm[i][lane] = load_xe_safe(xr, base + i * CH + 96 + lane);
            __syncwarp();
            int sbx = SEG_IDX(CPB * CH);
            EXT_OCTET(0,  sbx); EXT_OCTET(8,  sbx);
            EXT_OCTET(16, sbx); EXT_OCTET(24, sbx);
        }
    }

    __syncthreads();

    // ================= backward pass =================
    {
        bool fast = (b < BPR - 1) && !(b == 0 && wib == 0)
                    && !(b == BPR - 2 && wib == WPB - 1);
        float x1 = 0.f, x2 = 0.f, x3 = 0.f, x4 = 0.f;
        float y1 = 0.f, y2 = 0.f, y3 = 0.f, y4 = 0.f;

        if (fast) {
            // Recursion runs t = t0 down; j = t0 - t; u = q*CH + 95 - j.
            // tb=0 warm-up; tb=1,2 emit via tile -> coalesced desc stores.
            #pragma unroll
            for (int tb = 0; tb < TILES; ++tb) {
                int u0 = q * CH + 95 - tb * 32;
                int sb = SEG_IDX(u0);           // no 64-crossing inside tile
                if (tb == 0) {
                    BWD_OCTET(0,  false, sb); BWD_OCTET(8,  false, sb);
                    BWD_OCTET(16, false, sb); BWD_OCTET(24, false, sb);
                } else {
                    BWD_OCTET(0,  true, sb); BWD_OCTET(8,  true, sb);
                    BWD_OCTET(16, true, sb); BWD_OCTET(24, true, sb);
                    __syncwarp();
                    // t = A + (c0+i)*CH + 95 - (tb*32 + lane); out idx t-PAD
                    float* qp = orow + (A + c0 * CH + 95 - tb * 32 - PAD) - lane;
                    #pragma unroll 8
                    for (int i = 0; i < 32; ++i) qp[i * CH] = sm[i][lane];
                }
                __syncwarp();
            }
        } else {
            // scalar guarded path (block edges, row top, stub block)
            int emit_lo = A + q * CH;
            int emit_hi = emit_lo + CH - 1;
            int t0 = emit_hi + WARM;
            if (t0 > TEXT - 1) t0 = TEXT - 1;  // row top: exact zero-state start
            for (int t = t0; t >= emit_lo; --t) {
                float v = seg[SEG_IDX(t - A)];
                IIR_STEP(v);
                if (t <= emit_hi && t >= PAD && t < T_LEN + PAD)
                    orow[t - PAD] = y1;
            }
        }
    }
}

extern "C" void kernel_launch(void* const* d_in, const int* in_sizes, int n_in,
                              void* d_out, int out_size) {
    const float* x  = (const float*)d_in[0];
    const float* bc = (const float*)d_in[1];
    const float* ac = (const float*)d_in[2];
    float* out = (float*)d_out;

    int nrows  = in_sizes[0] / T_LEN;      // 512
    int blocks = nrows * BPR;              // 2560

    static int configured = 0;
    if (!configured) {
        cudaFuncSetAttribute(filt_kernel,
                             cudaFuncAttributeMaxDynamicSharedMemorySize,
                             SMEM_BYTES);
        configured = 1;
    }

    filt_kernel<<<blocks, BLOCK, SMEM_BYTES>>>(x, bc, ac, out);
}

// round 15
// speedup vs baseline: 1.1164x; 1.1164x over previous
#include <cuda_runtime.h>

// filtfilt (5-tap butter-style IIR, odd ext padlen=15) over 512 rows, T=32768.
//
// R15 = R12 (WARM=32, CH=64, 3 tiles/warp, NCH=544, WPR=17) with ALL FOUR
// global access streams vectorized to 128-bit via alignment algebra:
//  - chunk grid offset +3 (base = c0*64-29): fwd x-reads land on idx%4==0,
//  - forward scratch stored TIME-REVERSED, g[32798-t], with free register
//    component swizzle: fwd STG.128 aligned AND bwd reads become ascending
//    g[1+s] with (1+base)%4==0 -> LDG.128,
//  - bwd output quads start at 32779-s0 %4==0 -> reversed STG.128.
// Per-tile mem instrs: fwd 96->48, bwd 144->48 (issue-bound kernel).
// Chunk 0 emits t in {0,1,2} during warm-up (slow path) for full coverage.
// rel_err @ WARM=32 measured ~1.6e-4 (gate 1e-3).
// Reference's per-row scale/descale is a linear no-op, skipped.

#define T_LEN     32768
#define PAD       15
#define TEXT      (T_LEN + 2 * PAD)   // 32798
#define ROWSTRIDE 32800
#define MAXROWS   512
#define NCH       544                 // chunks per row (17 * 32)
#define CH        64
#define WARM      32
#define TILES     3                    // WIN = 96
#define WPR       17
#define WPB       4
#define BLOCK     (WPB * 32)           // 128
#define TW        36                   // tile row stride; 16B multiple
#define U0        32798                // g[u] = y_fwd[U0 - u - 0]; u = U0 - t

#define LD128(p)    (*reinterpret_cast<const float4*>(p))
#define ST128(p, v) (*reinterpret_cast<float4*>(p) = (v))

__device__ __align__(16) float g_fwd[(size_t)MAXROWS * ROWSTRIDE];

struct Coef {
    float b0, b1, b2, b3, b4;
    float na1, na2, na3, na4;
};

__device__ __forceinline__ Coef load_coef(const float* __restrict__ bc,
                                          const float* __restrict__ ac) {
    Coef c;
    float inva0 = 1.0f / ac[0];
    c.b0 = bc[0] * inva0; c.b1 = bc[1] * inva0; c.b2 = bc[2] * inva0;
    c.b3 = bc[3] * inva0; c.b4 = bc[4] * inva0;
    c.na1 = -ac[1] * inva0; c.na2 = -ac[2] * inva0;
    c.na3 = -ac[3] * inva0; c.na4 = -ac[4] * inva0;
    return c;
}

// Direct-Form-I step; critical chain is the final fma through y1 (4 cyc).
#define IIR_STEP(xt)                                                   \
    do {                                                               \
        float f = fmaf(c.b0, (xt), fmaf(c.b1, x1,                      \
                  fmaf(c.b2, x2, fmaf(c.b3, x3, c.b4 * x4))));         \
        float s_ = fmaf(c.na2, y2, fmaf(c.na3, y3,                     \
                   fmaf(c.na4, y4, f)));                               \
        float y = fmaf(c.na1, y1, s_);                                 \
        x4 = x3; x3 = x2; x2 = x1; x1 = (xt);                          \
        y4 = y3; y3 = y2; y2 = y1; y1 = y;                             \
    } while (0)

// 8 IIR steps on one octet of the tile, optional store-back.
#define P2_OCTET(jb, do_store)                                         \
    do {                                                               \
        float4 va = LD128(&sm[lane][jb]);                              \
        float4 vb = LD128(&sm[lane][(jb) + 4]);                        \
        float4 wa, wb;                                                 \
        IIR_STEP(va.x); wa.x = y1; IIR_STEP(va.y); wa.y = y1;          \
        IIR_STEP(va.z); wa.z = y1; IIR_STEP(va.w); wa.w = y1;          \
        IIR_STEP(vb.x); wb.x = y1; IIR_STEP(vb.y); wb.y = y1;          \
        IIR_STEP(vb.z); wb.z = y1; IIR_STEP(vb.w); wb.w = y1;          \
        if (do_store) {                                                \
            ST128(&sm[lane][jb], wa);                                  \
            ST128(&sm[lane][(jb) + 4], wb);                            \
        }                                                              \
    } while (0)

// Odd-extended input at extended index t; 0 outside [0, TEXT).
__device__ __forceinline__ float load_xe_safe(const float* __restrict__ xr, int t) {
    if (t < 0)            return 0.0f;
    if (t < PAD)          return 2.0f * xr[0]         - xr[PAD - t];
    if (t < T_LEN + PAD)  return xr[t - PAD];
    if (t < TEXT)         return 2.0f * xr[T_LEN - 1] - xr[2 * T_LEN + PAD - 2 - t];
    return 0.0f;
}

__global__ void __launch_bounds__(BLOCK)
fwd_kernel(const float* __restrict__ x,
           const float* __restrict__ bc,
           const float* __restrict__ ac) {
    int wib  = threadIdx.x >> 5;
    int lane = threadIdx.x & 31;
    int gw   = blockIdx.x * WPB + wib;
    int row  = gw / WPR;
    int wir  = gw - row * WPR;

    Coef c = load_coef(bc, ac);
    const float* xr = x + (size_t)row * T_LEN;
    float*       gr = g_fwd + (size_t)row * ROWSTRIDE;

    __shared__ __align__(16) float tile_s[WPB][32][TW];
    float (*sm)[TW] = tile_s[wib];

    int c0   = wir * 32;
    int base = c0 * CH - WARM + 3;      // == 3 (mod 4)
    bool fast = (wir != 0) && (wir != WPR - 1);
    int i0 = lane >> 3, q4 = (lane & 7) * 4;

    float x1 = 0.f, x2 = 0.f, x3 = 0.f, x4 = 0.f;
    float y1 = 0.f, y2 = 0.f, y3 = 0.f, y4 = 0.f;

    #pragma unroll
    for (int tl = 0; tl < TILES; ++tl) {
        int off = tl * 32;
        // Phase 1: tile fill. fast: LDG.128 + STS.128 (x idx base-15 == 0 mod 4).
        if (fast) {
            const float* p = xr + (base - PAD) + off;
            #pragma unroll
            for (int r8 = 0; r8 < 8; ++r8) {
                int i = r8 * 4 + i0;
                float4 v = LD128(p + i * CH + q4);
                ST128(&sm[i][q4], v);
            }
        } else {
            #pragma unroll 4
            for (int i = 0; i < 32; ++i)
                sm[i][lane] = load_xe_safe(xr, base + i * CH + off + lane);
        }
        __syncwarp();
        // Phase 2: 32 IIR steps; slow path stores all tiles (t<3 emission).
        bool st = (tl >= 1) || !fast;
        P2_OCTET(0,  st); P2_OCTET(8,  st);
        P2_OCTET(16, st); P2_OCTET(24, st);
        __syncwarp();
        // Phase 3: store TIME-REVERSED to g: g[U0 - t], reversed STG.128.
        if (fast) {
            if (tl >= 1) {
                const float* tp;
                float* qp = gr + (U0 - 3 - base - off);
                #pragma unroll
                for (int r8 = 0; r8 < 8; ++r8) {
                    int i = r8 * 4 + i0;
                    float4 v = LD128(&sm[i][q4]);
                    float4 w = make_float4(v.w, v.z, v.y, v.x);
                    ST128(qp - i * CH - q4, w);
                }
                (void)tp;
            }
        } else {
            // guarded scalar; chunk 0 also emits t in {0,1,2} from warm-up
            #pragma unroll 4
            for (int i = 0; i < 32; ++i) {
                int t = base + i * CH + off + lane;
                bool em = (off + lane >= WARM) || (t >= 0 && t < 3);
                if (em && t >= 0 && t < TEXT) gr[U0 - t] = sm[i][lane];
            }
        }
        __syncwarp();
    }
}

__global__ void __launch_bounds__(BLOCK)
bwd_kernel(const float* __restrict__ bc,
           const float* __restrict__ ac,
           float* __restrict__ out) {
    int wib  = threadIdx.x >> 5;
    int lane = threadIdx.x & 31;
    int gw   = blockIdx.x * WPB + wib;
    int row  = gw / WPR;
    int wir  = gw - row * WPR;

    Coef c = load_coef(bc, ac);
    const float* gr1  = g_fwd + (size_t)row * ROWSTRIDE + 1;  // g[1+s]
    float*       orow = out   + (size_t)row * T_LEN;

    __shared__ __align__(16) float tile_s[WPB][32][TW];
    float (*sm)[TW] = tile_s[wib];

    int c0   = wir * 32;
    int base = c0 * CH - WARM + 3;      // s-grid offset; (1+base) == 0 mod 4
    bool fast = (wir != 0) && (wir != WPR - 1);
    int i0 = lane >> 3, q4 = (lane & 7) * 4;

    float x1 = 0.f, x2 = 0.f, x3 = 0.f, x4 = 0.f;
    float y1 = 0.f, y2 = 0.f, y3 = 0.f, y4 = 0.f;

    #pragma unroll
    for (int tl = 0; tl < TILES; ++tl) {
        int off = tl * 32;
        // Phase 1: ascending reads of reversed scratch -> LDG.128 + STS.128.
        if (fast) {
            const float* p = gr1 + base + off;
            #pragma unroll
            for (int r8 = 0; r8 < 8; ++r8) {
                int i = r8 * 4 + i0;
                float4 v = LD128(p + i * CH + q4);
                ST128(&sm[i][q4], v);
            }
        } else {
            #pragma unroll 4
            for (int i = 0; i < 32; ++i) {
                int s = base + i * CH + off + lane;
                sm[i][lane] = (s >= 0 && s < TEXT) ? gr1[s] : 0.f;
            }
        }
        __syncwarp();
        bool st = (tl >= 1);
        P2_OCTET(0,  st); P2_OCTET(8,  st);
        P2_OCTET(16, st); P2_OCTET(24, st);
        __syncwarp();
        // Phase 3: out idx o = 32782 - s; quad start 32779-s0 == 0 mod 4:
        // reversed STG.128 (fast). Slow: guarded scalar.
        if (tl >= 1) {
            if (fast) {
                float* qp = orow + (32779 - base - off);
                #pragma unroll
                for (int r8 = 0; r8 < 8; ++r8) {
                    int i = r8 * 4 + i0;
                    float4 v = LD128(&sm[i][q4]);
                    float4 w = make_float4(v.w, v.z, v.y, v.x);
                    ST128(qp - i * CH - q4, w);
                }
            } else {
                #pragma unroll 4
                for (int i = 0; i < 32; ++i) {
                    int s = base + i * CH + off + lane;
                    int o = 32782 - s;
                    if (o >= 0 && o < T_LEN) orow[o] = sm[i][lane];
                }
            }
        }
        __syncwarp();
    }
}

extern "C" void kernel_launch(void* const* d_in, const int* in_sizes, int n_in,
                              void* d_out, int out_size) {
    const float* x  = (const float*)d_in[0];
    const float* bc = (const float*)d_in[1];
    const float* ac = (const float*)d_in[2];
    float* out = (float*)d_out;

    int nrows  = in_sizes[0] / T_LEN;          // 512
    int total_warps = nrows * WPR;             // 8704
    int blocks = total_warps / WPB;            // 2176 (exact)

    fwd_kernel<<<blocks, BLOCK>>>(x, bc, ac);
    bwd_kernel<<<blocks, BLOCK>>>(bc, ac, out);
}